// round 3
// baseline (speedup 1.0000x reference)
#include <cuda_runtime.h>
#include <math.h>

#define BB 32
#define QQ 1024
#define KKD 1024
#define DD 64
#define TQ 32
#define TK 128

// smem layout (floats):
//   sQ  [32][68]     = 2176        (reused as context accumulator at end)
//   sKV max(128*68, 64*132) = 8704 (K tile in phase1, V^T tile in phase2)
//   sSc [32][1028]   = 32896       (scores -> probabilities)
#define SQ_OFF   0
#define SKV_OFF  (TQ*68)
#define SSC_OFF  (SKV_OFF + TK*68)
#define SMEM_FLOATS (SSC_OFF + TQ*1028)
#define SMEM_BYTES (SMEM_FLOATS * 4)

// 1 = mask is a byte array (bool8), 0 = mask is int32 (0/1)
__device__ int g_mask_is_u8;

__global__ void detect_mask_dtype(const unsigned char* __restrict__ m)
{
    // If the mask were int32 with values 0/1, every byte at offset %4 != 0 is 0.
    // If it is a byte mask (~50% nonzero), offsets %4 != 0 will hit nonzero
    // bytes with overwhelming probability within 64KB.
    int found = 0;
    for (int i = threadIdx.x; i < 65536; i += blockDim.x) {
        if ((i & 3) != 0 && m[i] != 0) found = 1;
    }
    int any = __syncthreads_or(found);
    if (threadIdx.x == 0) g_mask_is_u8 = any;
}

__global__ __launch_bounds__(256, 1)
void sdpa_kernel(const float* __restrict__ gq,
                 const float* __restrict__ gk,
                 const float* __restrict__ gv,
                 const unsigned char* __restrict__ gmask,
                 float* __restrict__ out_ctx,
                 float* __restrict__ out_attn)
{
    extern __shared__ float smem[];
    float* sQ  = smem + SQ_OFF;
    float* sKV = smem + SKV_OFF;
    float* sSc = smem + SSC_OFF;

    const int b   = blockIdx.y;
    const int q0  = blockIdx.x * TQ;
    const int tid = threadIdx.x;
    const int lane = tid & 31;
    const int mask_u8 = g_mask_is_u8;

    // ---- load Q tile [32][64] into sQ (rows padded to 68) ----
    {
        const float* qsrc = gq + ((size_t)b * QQ + q0) * DD;
        #pragma unroll
        for (int it = 0; it < 2; ++it) {
            int idx = tid + it * 256;       // 0..511 float4s
            int row = idx >> 4;
            int col = (idx & 15) << 2;
            *(float4*)(sQ + row * 68 + col) =
                *(const float4*)(qsrc + row * DD + col);
        }
    }

    // ---- Phase 1: scores = Q K^T / 8, masked, into sSc ----
    const int qg = tid >> 5;                 // 8 q-groups of 4 rows
    for (int kt = 0; kt < KKD / TK; ++kt) {
        const int k0 = kt * TK;
        __syncthreads();                     // sKV free (also covers Q load on iter 0)
        const float* ksrc = gk + ((size_t)b * KKD + k0) * DD;
        #pragma unroll
        for (int it = 0; it < 8; ++it) {
            int idx = tid + it * 256;        // 0..2047 float4s
            int row = idx >> 4;
            int col = (idx & 15) << 2;
            *(float4*)(sKV + row * 68 + col) =
                *(const float4*)(ksrc + row * DD + col);
        }
        __syncthreads();

        float acc[4][4];
        #pragma unroll
        for (int j = 0; j < 4; ++j)
            #pragma unroll
            for (int i = 0; i < 4; ++i) acc[j][i] = 0.f;

        #pragma unroll
        for (int dq = 0; dq < 16; ++dq) {
            int d = dq << 2;
            float4 qv[4], kv[4];
            #pragma unroll
            for (int j = 0; j < 4; ++j)
                qv[j] = *(const float4*)(sQ + (qg * 4 + j) * 68 + d);
            #pragma unroll
            for (int i = 0; i < 4; ++i)
                kv[i] = *(const float4*)(sKV + (lane + 32 * i) * 68 + d);
            #pragma unroll
            for (int j = 0; j < 4; ++j)
                #pragma unroll
                for (int i = 0; i < 4; ++i)
                    acc[j][i] += qv[j].x * kv[i].x + qv[j].y * kv[i].y
                               + qv[j].z * kv[i].z + qv[j].w * kv[i].w;
        }

        #pragma unroll
        for (int j = 0; j < 4; ++j) {
            int qr = qg * 4 + j;
            const size_t moff = ((size_t)b * QQ + q0 + qr) * KKD + k0;
            const unsigned char* mrow8 = gmask + moff;
            const int* mrow32 = (const int*)gmask + moff;
            #pragma unroll
            for (int i = 0; i < 4; ++i) {
                int kc = lane + 32 * i;
                float s = acc[j][i] * 0.125f;      // 1/sqrt(64), exact
                int masked = mask_u8 ? (int)mrow8[kc] : mrow32[kc];
                if (masked) s = -1e9f;             // mask==True -> NEG_INF
                sSc[qr * 1028 + k0 + kc] = s;
            }
        }
    }
    __syncthreads();

    // ---- Softmax per row (warp handles 4 rows), write attn ----
    {
        int w = tid >> 5;
        #pragma unroll
        for (int rr = 0; rr < 4; ++rr) {
            int r = w * 4 + rr;
            float* row = sSc + r * 1028;
            float m = -3.4e38f;
            #pragma unroll
            for (int t = 0; t < 32; ++t)
                m = fmaxf(m, row[lane + 32 * t]);
            #pragma unroll
            for (int o = 16; o > 0; o >>= 1)
                m = fmaxf(m, __shfl_xor_sync(0xffffffffu, m, o));
            float sum = 0.f;
            #pragma unroll
            for (int t = 0; t < 32; ++t) {
                float p = __expf(row[lane + 32 * t] - m);
                row[lane + 32 * t] = p;
                sum += p;
            }
            #pragma unroll
            for (int o = 16; o > 0; o >>= 1)
                sum += __shfl_xor_sync(0xffffffffu, sum, o);
            float inv = 1.f / sum;
            float* adst = out_attn + ((size_t)b * QQ + q0 + r) * KKD;
            #pragma unroll
            for (int t = 0; t < 32; ++t) {
                float p = row[lane + 32 * t] * inv;
                row[lane + 32 * t] = p;
                adst[lane + 32 * t] = p;
            }
        }
    }

    // ---- Phase 2: context = P @ V ----
    const int half = tid >> 7;      // k-split across thread halves
    const int t2   = tid & 127;
    const int qg2  = t2 >> 4;       // 8 groups of 4 q rows
    const int dg   = t2 & 15;       // 16 groups; d_i = dg + 16*i
    float cacc[4][4];
    #pragma unroll
    for (int j = 0; j < 4; ++j)
        #pragma unroll
        for (int i = 0; i < 4; ++i) cacc[j][i] = 0.f;

    for (int kt = 0; kt < KKD / TK; ++kt) {
        const int k0 = kt * TK;
        __syncthreads();
        // load V tile transposed: sKV[d][k], row stride 132 (conflict-free)
        const float* vsrc = gv + ((size_t)b * KKD + k0) * DD;
        {
            int d = tid & 63;
            int kqbase = tid >> 6;     // 0..3
            #pragma unroll
            for (int it = 0; it < 8; ++it) {
                int kq4 = it * 4 + kqbase;   // 0..31
                int kk = kq4 * 4;
                float v0 = vsrc[(kk + 0) * DD + d];   // 128B coalesced per warp
                float v1 = vsrc[(kk + 1) * DD + d];
                float v2 = vsrc[(kk + 2) * DD + d];
                float v3 = vsrc[(kk + 3) * DD + d];
                *(float4*)(sKV + d * 132 + kk) = make_float4(v0, v1, v2, v3);
            }
        }
        __syncthreads();
        #pragma unroll
        for (int kq = 0; kq < 16; ++kq) {
            int k = half * 64 + kq * 4;
            float4 pv[4], vv[4];
            #pragma unroll
            for (int j = 0; j < 4; ++j)
                pv[j] = *(const float4*)(sSc + (qg2 * 4 + j) * 1028 + k0 + k);
            #pragma unroll
            for (int i = 0; i < 4; ++i)
                vv[i] = *(const float4*)(sKV + (dg + 16 * i) * 132 + k);
            #pragma unroll
            for (int j = 0; j < 4; ++j)
                #pragma unroll
                for (int i = 0; i < 4; ++i)
                    cacc[j][i] += pv[j].x * vv[i].x + pv[j].y * vv[i].y
                                + pv[j].z * vv[i].z + pv[j].w * vv[i].w;
        }
    }

    // reduce the two k-halves via sQ (reused as context tile [32][68])
    float* sC = sQ;
    __syncthreads();
    if (half == 0) {
        #pragma unroll
        for (int j = 0; j < 4; ++j)
            #pragma unroll
            for (int i = 0; i < 4; ++i)
                sC[(qg2 * 4 + j) * 68 + dg + 16 * i] = cacc[j][i];
    }
    __syncthreads();
    if (half == 1) {
        #pragma unroll
        for (int j = 0; j < 4; ++j)
            #pragma unroll
            for (int i = 0; i < 4; ++i)
                sC[(qg2 * 4 + j) * 68 + dg + 16 * i] += cacc[j][i];
    }
    __syncthreads();

    // write context tile
    {
        float* cdst = out_ctx + ((size_t)b * QQ + q0) * DD;
        #pragma unroll
        for (int it = 0; it < 2; ++it) {
            int idx = tid + it * 256;
            int row = idx >> 4;
            int col = (idx & 15) << 2;
            *(float4*)(cdst + row * DD + col) =
                *(const float4*)(sC + row * 68 + col);
        }
    }
}

extern "C" void kernel_launch(void* const* d_in, const int* in_sizes, int n_in,
                              void* d_out, int out_size)
{
    const float* q = (const float*)d_in[0];
    const float* k = (const float*)d_in[1];
    const float* v = (const float*)d_in[2];
    const unsigned char* mask = (const unsigned char*)d_in[3];

    float* ctx  = (float*)d_out;                      // [B,Q,D] first
    float* attn = ctx + (size_t)BB * QQ * DD;         // [B,Q,K] second

    detect_mask_dtype<<<1, 256>>>(mask);

    cudaFuncSetAttribute(sdpa_kernel,
                         cudaFuncAttributeMaxDynamicSharedMemorySize,
                         SMEM_BYTES);
    dim3 grid(QQ / TQ, BB);
    sdpa_kernel<<<grid, 256, SMEM_BYTES>>>(q, k, v, mask, ctx, attn);
}

// round 5
// speedup vs baseline: 1.1253x; 1.1253x over previous
#include <cuda_runtime.h>
#include <math.h>

#define BB 32
#define QQ 1024
#define KKD 1024
#define DD 64
#define TQ 32
#define TK 256

// smem layout (floats):
//   sQ  [32][68]       = 2176      (reused as context accumulator at end)
//   sKV max(256*68, 64*260) = 17408  (K tile phase1 / V^T tile phase2)
//   sSc [32][1028]     = 32896     (scores -> probabilities)
#define SQ_OFF   0
#define SKV_OFF  (TQ*68)
#define SSC_OFF  (SKV_OFF + TK*68)
#define SMEM_FLOATS (SSC_OFF + TQ*1028)
#define SMEM_BYTES (SMEM_FLOATS * 4)   // 209,920 B — fits 227KB, 1 CTA/SM

// 1 = mask is a byte array (bool8), 0 = mask is int32 (0/1)
__device__ int g_mask_is_u8;

__global__ void detect_mask_dtype(const unsigned char* __restrict__ m)
{
    int found = 0;
    for (int i = threadIdx.x; i < 65536; i += blockDim.x) {
        if ((i & 3) != 0 && m[i] != 0) found = 1;
    }
    int any = __syncthreads_or(found);
    if (threadIdx.x == 0) g_mask_is_u8 = any;
}

// packed fp32x2 FMA (FFMA2) — only reachable via PTX on sm_103a
__device__ __forceinline__ unsigned long long ffma2(unsigned long long a,
                                                    unsigned long long b,
                                                    unsigned long long c)
{
    unsigned long long d;
    asm("fma.rn.f32x2 %0, %1, %2, %3;" : "=l"(d) : "l"(a), "l"(b), "l"(c));
    return d;
}

__device__ __forceinline__ float hsum2(unsigned long long p)
{
    float2 f = *reinterpret_cast<float2*>(&p);
    return f.x + f.y;
}

__global__ __launch_bounds__(256, 1)
void sdpa_kernel(const float* __restrict__ gq,
                 const float* __restrict__ gk,
                 const float* __restrict__ gv,
                 const unsigned char* __restrict__ gmask,
                 float* __restrict__ out_ctx,
                 float* __restrict__ out_attn)
{
    extern __shared__ float smem[];
    float* sQ  = smem + SQ_OFF;
    float* sKV = smem + SKV_OFF;
    float* sSc = smem + SSC_OFF;

    const int b   = blockIdx.y;
    const int q0  = blockIdx.x * TQ;
    const int tid = threadIdx.x;
    const int lane = tid & 31;
    const int mask_u8 = g_mask_is_u8;

    // ---- load Q tile [32][64] into sQ (rows padded to 68) ----
    {
        const float* qsrc = gq + ((size_t)b * QQ + q0) * DD;
        #pragma unroll
        for (int it = 0; it < 2; ++it) {
            int idx = tid + it * 256;       // 0..511 float4s
            int row = idx >> 4;
            int col = (idx & 15) << 2;
            *(float4*)(sQ + row * 68 + col) =
                *(const float4*)(qsrc + row * DD + col);
        }
    }

    // ---- Phase 1: scores = Q K^T / 8, masked, into sSc ----
    // per thread: 4 q-rows (warp id) x 8 k-cols (lane + 32*i), f32x2 accumulators
    const int qg = tid >> 5;                 // 8 warps = 8 q-groups of 4 rows
    for (int kt = 0; kt < KKD / TK; ++kt) {  // 4 tiles of 256 k
        const int k0 = kt * TK;
        __syncthreads();                     // sKV free (covers Q load on iter 0)
        const float* ksrc = gk + ((size_t)b * KKD + k0) * DD;
        #pragma unroll
        for (int it = 0; it < 16; ++it) {
            int idx = tid + it * 256;        // 0..4095 float4s (256 rows x 16)
            int row = idx >> 4;
            int col = (idx & 15) << 2;
            *(float4*)(sKV + row * 68 + col) =
                *(const float4*)(ksrc + row * DD + col);
        }
        __syncthreads();

        unsigned long long acc2[4][8];
        #pragma unroll
        for (int j = 0; j < 4; ++j)
            #pragma unroll
            for (int i = 0; i < 8; ++i) acc2[j][i] = 0ull;

        #pragma unroll
        for (int dq = 0; dq < 16; ++dq) {
            int d = dq << 2;
            float4 qv[4], kv[8];
            #pragma unroll
            for (int j = 0; j < 4; ++j)      // warp-broadcast loads (free)
                qv[j] = *(const float4*)(sQ + (qg * 4 + j) * 68 + d);
            #pragma unroll
            for (int i = 0; i < 8; ++i)
                kv[i] = *(const float4*)(sKV + (lane + 32 * i) * 68 + d);
            #pragma unroll
            for (int j = 0; j < 4; ++j) {
                const unsigned long long* qp = (const unsigned long long*)&qv[j];
                #pragma unroll
                for (int i = 0; i < 8; ++i) {
                    const unsigned long long* kp = (const unsigned long long*)&kv[i];
                    acc2[j][i] = ffma2(qp[0], kp[0], acc2[j][i]);
                    acc2[j][i] = ffma2(qp[1], kp[1], acc2[j][i]);
                }
            }
        }

        #pragma unroll
        for (int j = 0; j < 4; ++j) {
            int qr = qg * 4 + j;
            const size_t moff = ((size_t)b * QQ + q0 + qr) * KKD + k0;
            const unsigned char* mrow8 = gmask + moff;
            const int* mrow32 = (const int*)gmask + moff;
            #pragma unroll
            for (int i = 0; i < 8; ++i) {
                int kc = lane + 32 * i;
                float s = hsum2(acc2[j][i]) * 0.125f;   // 1/sqrt(64), exact
                int masked = mask_u8 ? (int)mrow8[kc] : mrow32[kc];
                if (masked) s = -1e9f;                  // mask==True -> NEG_INF
                sSc[qr * 1028 + k0 + kc] = s;
            }
        }
    }
    __syncthreads();

    // ---- Softmax per row (warp handles 4 rows), write attn ----
    {
        int w = tid >> 5;
        #pragma unroll
        for (int rr = 0; rr < 4; ++rr) {
            int r = w * 4 + rr;
            float* row = sSc + r * 1028;
            float m = -3.4e38f;
            #pragma unroll
            for (int t = 0; t < 32; ++t)
                m = fmaxf(m, row[lane + 32 * t]);
            #pragma unroll
            for (int o = 16; o > 0; o >>= 1)
                m = fmaxf(m, __shfl_xor_sync(0xffffffffu, m, o));
            float sum = 0.f;
            #pragma unroll
            for (int t = 0; t < 32; ++t) {
                float p = __expf(row[lane + 32 * t] - m);
                row[lane + 32 * t] = p;
                sum += p;
            }
            #pragma unroll
            for (int o = 16; o > 0; o >>= 1)
                sum += __shfl_xor_sync(0xffffffffu, sum, o);
            float inv = 1.f / sum;
            float* adst = out_attn + ((size_t)b * QQ + q0 + r) * KKD;
            #pragma unroll
            for (int t = 0; t < 32; ++t) {
                float p = row[lane + 32 * t] * inv;
                row[lane + 32 * t] = p;
                adst[lane + 32 * t] = p;
            }
        }
    }

    // ---- Phase 2: context = P @ V (f32x2 over k) ----
    const int half = tid >> 7;      // k-split across thread halves
    const int t2   = tid & 127;
    const int qg2  = t2 >> 4;       // 8 groups of 4 q rows
    const int dg   = t2 & 15;       // 16 groups; d_i = dg + 16*i
    unsigned long long cacc2[4][4];
    #pragma unroll
    for (int j = 0; j < 4; ++j)
        #pragma unroll
        for (int i = 0; i < 4; ++i) cacc2[j][i] = 0ull;

    for (int kt = 0; kt < KKD / TK; ++kt) {
        const int k0 = kt * TK;
        __syncthreads();
        // load V tile transposed: sKV[d][k], row stride 260
        const float* vsrc = gv + ((size_t)b * KKD + k0) * DD;
        {
            int d = tid & 63;
            int kqbase = tid >> 6;     // 0..3
            #pragma unroll
            for (int it = 0; it < 16; ++it) {
                int kq4 = it * 4 + kqbase;   // 0..63
                int kk = kq4 * 4;
                float v0 = vsrc[(kk + 0) * DD + d];   // 256B coalesced per row
                float v1 = vsrc[(kk + 1) * DD + d];
                float v2 = vsrc[(kk + 2) * DD + d];
                float v3 = vsrc[(kk + 3) * DD + d];
                *(float4*)(sKV + d * 260 + kk) = make_float4(v0, v1, v2, v3);
            }
        }
        __syncthreads();
        #pragma unroll
        for (int kq = 0; kq < 32; ++kq) {
            int k = half * 128 + kq * 4;
            float4 pv[4], vv[4];
            #pragma unroll
            for (int j = 0; j < 4; ++j)
                pv[j] = *(const float4*)(sSc + (qg2 * 4 + j) * 1028 + k0 + k);
            #pragma unroll
            for (int i = 0; i < 4; ++i)
                vv[i] = *(const float4*)(sKV + (dg + 16 * i) * 260 + k);
            #pragma unroll
            for (int j = 0; j < 4; ++j) {
                const unsigned long long* pp = (const unsigned long long*)&pv[j];
                #pragma unroll
                for (int i = 0; i < 4; ++i) {
                    const unsigned long long* vp = (const unsigned long long*)&vv[i];
                    cacc2[j][i] = ffma2(pp[0], vp[0], cacc2[j][i]);
                    cacc2[j][i] = ffma2(pp[1], vp[1], cacc2[j][i]);
                }
            }
        }
    }

    // reduce the two k-halves via sQ (reused as context tile [32][68])
    float* sC = sQ;
    __syncthreads();
    if (half == 0) {
        #pragma unroll
        for (int j = 0; j < 4; ++j)
            #pragma unroll
            for (int i = 0; i < 4; ++i)
                sC[(qg2 * 4 + j) * 68 + dg + 16 * i] = hsum2(cacc2[j][i]);
    }
    __syncthreads();
    if (half == 1) {
        #pragma unroll
        for (int j = 0; j < 4; ++j)
            #pragma unroll
            for (int i = 0; i < 4; ++i)
                sC[(qg2 * 4 + j) * 68 + dg + 16 * i] += hsum2(cacc2[j][i]);
    }
    __syncthreads();

    // write context tile
    {
        float* cdst = out_ctx + ((size_t)b * QQ + q0) * DD;
        #pragma unroll
        for (int it = 0; it < 2; ++it) {
            int idx = tid + it * 256;
            int row = idx >> 4;
            int col = (idx & 15) << 2;
            *(float4*)(cdst + row * DD + col) =
                *(const float4*)(sC + row * 68 + col);
        }
    }
}

extern "C" void kernel_launch(void* const* d_in, const int* in_sizes, int n_in,
                              void* d_out, int out_size)
{
    const float* q = (const float*)d_in[0];
    const float* k = (const float*)d_in[1];
    const float* v = (const float*)d_in[2];
    const unsigned char* mask = (const unsigned char*)d_in[3];

    float* ctx  = (float*)d_out;                      // [B,Q,D] first
    float* attn = ctx + (size_t)BB * QQ * DD;         // [B,Q,K] second

    detect_mask_dtype<<<1, 256>>>(mask);

    cudaFuncSetAttribute(sdpa_kernel,
                         cudaFuncAttributeMaxDynamicSharedMemorySize,
                         SMEM_BYTES);
    dim3 grid(QQ / TQ, BB);
    sdpa_kernel<<<grid, 256, SMEM_BYTES>>>(q, k, v, mask, ctx, attn);
}

// round 15
// speedup vs baseline: 1.2798x; 1.1372x over previous
#include <cuda_runtime.h>
#include <cuda_bf16.h>
#include <math.h>
#include <stdint.h>

#define BB 32
#define QQ 1024
#define KK 1024
#define DD 64
#define QT 128
#define NT 8            // k tiles of 128  (KK/128 — was wrongly 4 in R7-R9)

// ---- smem layout (bytes) ----
// pass A: bf16 tiles
#define T_STRIDE 144            // 72 bf16 per row (64 + 8 pad)
#define T_SZ (128 * T_STRIDE)   // 18432
#define OFF_QH 0
#define OFF_QL T_SZ
#define OFF_KH (2 * T_SZ)
#define OFF_KL (3 * T_SZ)
// pass B overlay: f32 V^T [64][132] + f32 P [128][132]
#define PB_STRIDE 132
#define OFF_VT 0
#define OFF_PF 34816
#define SMEM_BYTES 102400

static __device__ __forceinline__ uint32_t smem_u32(const void* p) {
    uint32_t a;
    asm("{ .reg .u64 t; cvta.to.shared.u64 t, %1; cvt.u32.u64 %0, t; }" : "=r"(a) : "l"(p));
    return a;
}

static __device__ __forceinline__ void ldsm4(uint32_t* r, uint32_t addr) {
    asm volatile("ldmatrix.sync.aligned.m8n8.x4.shared.b16 {%0,%1,%2,%3}, [%4];"
                 : "=r"(r[0]), "=r"(r[1]), "=r"(r[2]), "=r"(r[3]) : "r"(addr));
}
static __device__ __forceinline__ void mma16816(float* c, const uint32_t* a,
                                                uint32_t b0, uint32_t b1) {
    asm volatile("mma.sync.aligned.m16n8k16.row.col.f32.bf16.bf16.f32 "
                 "{%0,%1,%2,%3}, {%4,%5,%6,%7}, {%8,%9}, {%0,%1,%2,%3};"
                 : "+f"(c[0]), "+f"(c[1]), "+f"(c[2]), "+f"(c[3])
                 : "r"(a[0]), "r"(a[1]), "r"(a[2]), "r"(a[3]), "r"(b0), "r"(b1));
}

// packed fp32x2 FMA (verified in R4)
static __device__ __forceinline__ unsigned long long ffma2(unsigned long long a,
                                                           unsigned long long b,
                                                           unsigned long long c) {
    unsigned long long d;
    asm("fma.rn.f32x2 %0, %1, %2, %3;" : "=l"(d) : "l"(a), "l"(b), "l"(c));
    return d;
}
static __device__ __forceinline__ float hsum2(unsigned long long p) {
    float2 f = *reinterpret_cast<float2*>(&p);
    return f.x + f.y;
}

// fp32 pair -> bf16 hi pair + bf16 lo (residual) pair
static __device__ __forceinline__ void split2(float x, float y, uint32_t& hi, uint32_t& lo) {
    __nv_bfloat162 h = __floats2bfloat162_rn(x, y);
    float rx = x - __bfloat162float(h.x);
    float ry = y - __bfloat162float(h.y);
    __nv_bfloat162 l = __floats2bfloat162_rn(rx, ry);
    hi = *(uint32_t*)&h;
    lo = *(uint32_t*)&l;
}

// [128][64] f32 tile -> bf16 hi/lo tiles with T_STRIDE rows
static __device__ __forceinline__ void conv_tile(const float* __restrict__ src,
                                                 char* hi, char* lo, int tid) {
#pragma unroll
    for (int it = 0; it < 8; ++it) {
        int idx = tid + it * 256;
        int row = idx >> 4;
        int c4  = (idx & 15) << 2;
        float4 v = *(const float4*)(src + row * DD + c4);
        uint32_t h0, l0, h1, l1;
        split2(v.x, v.y, h0, l0);
        split2(v.z, v.w, h1, l1);
        *(uint2*)(hi + row * T_STRIDE + c4 * 2) = make_uint2(h0, h1);
        *(uint2*)(lo + row * T_STRIDE + c4 * 2) = make_uint2(l0, l1);
    }
}

// 1 = byte mask, 0 = int32 mask
__device__ int g_mask_is_u8;
__global__ void detect_mask_dtype(const unsigned char* __restrict__ m) {
    int found = 0;
    for (int i = threadIdx.x; i < 65536; i += blockDim.x)
        if ((i & 3) != 0 && m[i] != 0) found = 1;
    int any = __syncthreads_or(found);
    if (threadIdx.x == 0) g_mask_is_u8 = any;
}

__global__ __launch_bounds__(256, 1)
void sdpa_hyb_kernel(const float* __restrict__ gq,
                     const float* __restrict__ gk,
                     const float* __restrict__ gv,
                     const unsigned char* __restrict__ gmask,
                     float* __restrict__ out_ctx,
                     float* __restrict__ out_attn)
{
    extern __shared__ char smem[];
    const uint32_t su = smem_u32(smem);

    const int tid  = threadIdx.x;
    const int wid  = tid >> 5;
    const int lane = tid & 31;
    const int b    = blockIdx.y;
    const int q0   = blockIdx.x * QT;
    const int mrow = wid * 16;
    const int mask_u8 = g_mask_is_u8;

    // fragment lane geometry (pass A)
    const int rowA = (lane & 7) + ((lane >> 3) & 1) * 8;
    const int colA = (lane >> 4) * 8;
    const int rowB = (lane & 7) + (lane >> 4) * 8;
    const int colB = ((lane >> 3) & 1) * 8;

    const uint32_t aQHa = su + OFF_QH + (mrow + rowA) * T_STRIDE + colA * 2;
    const uint32_t aQLa = su + OFF_QL + (mrow + rowA) * T_STRIDE + colA * 2;
    const uint32_t bKHa = su + OFF_KH + rowB * T_STRIDE + colB * 2;
    const uint32_t bKLa = su + OFF_KL + rowB * T_STRIDE + colB * 2;

    // per-thread output rows (pass A epilogue + normalize stage)
    const int r1loc = mrow + (lane >> 2);
    const size_t arow1 = ((size_t)b * QQ + q0 + r1loc) * (size_t)KK;
    const size_t arow2 = arow1 + 8 * (size_t)KK;
    const int coff = (lane & 3) * 2;
    const int* gm32 = (const int*)gmask;

    // ---- Q tile -> bf16 hi/lo ----
    conv_tile(gq + ((size_t)b * QQ + q0) * DD, smem + OFF_QH, smem + OFF_QL, tid);
    __syncthreads();

    uint32_t aQH[4][4], aQL[4][4];
#pragma unroll
    for (int ks = 0; ks < 4; ++ks) {
        ldsm4(aQH[ks], aQHa + ks * 32);
        ldsm4(aQL[ks], aQLa + ks * 32);
    }

    float m0 = -3.4e38f, l0 = 0.f, m1 = -3.4e38f, l1 = 0.f;

    // ================= PASS A (HMMA): raw masked scores + (m,l) =================
    for (int t = 0; t < NT; ++t) {
        const int k0 = t * 128;
        __syncthreads();
        conv_tile(gk + ((size_t)b * KK + k0) * DD, smem + OFF_KH, smem + OFF_KL, tid);
        __syncthreads();

        float c[16][4];
#pragma unroll
        for (int nb = 0; nb < 16; ++nb)
#pragma unroll
            for (int j = 0; j < 4; ++j) c[nb][j] = 0.f;

#pragma unroll
        for (int ks = 0; ks < 4; ++ks) {
#pragma unroll
            for (int nb2 = 0; nb2 < 8; ++nb2) {
                uint32_t bh[4], bl[4];
                const uint32_t boff = nb2 * (16 * T_STRIDE) + ks * 32;
                ldsm4(bh, bKHa + boff);
                ldsm4(bl, bKLa + boff);
                mma16816(c[nb2 * 2],     aQH[ks], bh[0], bh[1]);
                mma16816(c[nb2 * 2],     aQH[ks], bl[0], bl[1]);
                mma16816(c[nb2 * 2],     aQL[ks], bh[0], bh[1]);
                mma16816(c[nb2 * 2 + 1], aQH[ks], bh[2], bh[3]);
                mma16816(c[nb2 * 2 + 1], aQH[ks], bl[2], bl[3]);
                mma16816(c[nb2 * 2 + 1], aQL[ks], bh[2], bh[3]);
            }
        }

        float tmax0 = -3.4e38f, tmax1 = -3.4e38f;
#pragma unroll
        for (int nb = 0; nb < 16; ++nb) {
            const int col = k0 + nb * 8 + coff;
            float s0 = c[nb][0] * 0.125f, s1 = c[nb][1] * 0.125f;
            float s2 = c[nb][2] * 0.125f, s3 = c[nb][3] * 0.125f;
            if (mask_u8) {
                const unsigned char* p1 = gmask + arow1 + col;
                const unsigned char* p2 = gmask + arow2 + col;
                if (p1[0]) s0 = -1e9f;
                if (p1[1]) s1 = -1e9f;
                if (p2[0]) s2 = -1e9f;
                if (p2[1]) s3 = -1e9f;
            } else {
                int2 mA = __ldcs((const int2*)(gm32 + arow1 + col));
                int2 mB = __ldcs((const int2*)(gm32 + arow2 + col));
                if (mA.x) s0 = -1e9f;
                if (mA.y) s1 = -1e9f;
                if (mB.x) s2 = -1e9f;
                if (mB.y) s3 = -1e9f;
            }
            *(float2*)(out_attn + arow1 + col) = make_float2(s0, s1);
            *(float2*)(out_attn + arow2 + col) = make_float2(s2, s3);
            c[nb][0] = s0; c[nb][1] = s1; c[nb][2] = s2; c[nb][3] = s3;
            tmax0 = fmaxf(tmax0, fmaxf(s0, s1));
            tmax1 = fmaxf(tmax1, fmaxf(s2, s3));
        }
        float mn0 = fmaxf(m0, tmax0);
        float mn1 = fmaxf(m1, tmax1);
        float ps0 = 0.f, ps1 = 0.f;
#pragma unroll
        for (int nb = 0; nb < 16; ++nb) {
            ps0 += __expf(c[nb][0] - mn0) + __expf(c[nb][1] - mn0);
            ps1 += __expf(c[nb][2] - mn1) + __expf(c[nb][3] - mn1);
        }
        l0 = l0 * __expf(m0 - mn0) + ps0;
        l1 = l1 * __expf(m1 - mn1) + ps1;
        m0 = mn0;
        m1 = mn1;
    }

    // combine (m,l) across the 4 lanes of each row quad
#pragma unroll
    for (int o = 1; o <= 2; o <<= 1) {
        float mo = __shfl_xor_sync(0xffffffffu, m0, o);
        float lo = __shfl_xor_sync(0xffffffffu, l0, o);
        float mm = fmaxf(m0, mo);
        l0 = l0 * __expf(m0 - mm) + lo * __expf(mo - mm);
        m0 = mm;
        mo = __shfl_xor_sync(0xffffffffu, m1, o);
        lo = __shfl_xor_sync(0xffffffffu, l1, o);
        mm = fmaxf(m1, mo);
        l1 = l1 * __expf(m1 - mm) + lo * __expf(mo - mm);
        m1 = mm;
    }
    const float il0 = 1.f / l0;
    const float il1 = 1.f / l1;

    // ============ PASS B (SIMT f32x2, R4-verified style): attn + O = P V ============
    float* sVT = (float*)(smem + OFF_VT);   // [64][132] f32, V^T
    float* sP  = (float*)(smem + OFF_PF);   // [128][132] f32

    const int qgB = tid >> 4;      // 0..15 -> rows qgB + 16j, j=0..7
    const int dgB = tid & 15;      // 0..15 -> d = dgB + 16i, i=0..3

    unsigned long long acc2[8][4];
#pragma unroll
    for (int j = 0; j < 8; ++j)
#pragma unroll
        for (int i = 0; i < 4; ++i) acc2[j][i] = 0ull;

    for (int t = 0; t < NT; ++t) {
        const int k0 = t * 128;
        __syncthreads();   // prior iter's reads (and pass A smem use) done

        // stage V^T: sVT[d][k]
        {
            const float* vsrc = gv + ((size_t)b * KK + k0) * DD;
            int d = tid & 63;
            int kqb = tid >> 6;     // 0..3
#pragma unroll
            for (int it = 0; it < 8; ++it) {
                int kk = (it * 4 + kqb) * 4;     // 0..124
                float v0 = vsrc[(kk + 0) * DD + d];
                float v1 = vsrc[(kk + 1) * DD + d];
                float v2 = vsrc[(kk + 2) * DD + d];
                float v3 = vsrc[(kk + 3) * DD + d];
                *(float4*)(sVT + d * PB_STRIDE + kk) = make_float4(v0, v1, v2, v3);
            }
        }

        // normalize raw scores -> attn out + stage P f32 in smem
        {
            float* p1 = sP + r1loc * PB_STRIDE;
            float* p2 = p1 + 8 * PB_STRIDE;
#pragma unroll
            for (int nb = 0; nb < 16; ++nb) {
                const int col  = k0 + nb * 8 + coff;
                const int lcol = nb * 8 + coff;
                float2 sA = *(const float2*)(out_attn + arow1 + col);
                float2 sB = *(const float2*)(out_attn + arow2 + col);
                float pa = __expf(sA.x - m0) * il0;
                float pb = __expf(sA.y - m0) * il0;
                float pc = __expf(sB.x - m1) * il1;
                float pd = __expf(sB.y - m1) * il1;
                __stcs((float2*)(out_attn + arow1 + col), make_float2(pa, pb));
                __stcs((float2*)(out_attn + arow2 + col), make_float2(pc, pd));
                *(float2*)(p1 + lcol) = make_float2(pa, pb);
                *(float2*)(p2 + lcol) = make_float2(pc, pd);
            }
        }
        __syncthreads();

        // O += P @ V  (f32x2; thread: 8 q rows x 4 d)
#pragma unroll 4
        for (int kq = 0; kq < 32; ++kq) {
            const int k = kq * 4;
            float4 pv[8], vv[4];
#pragma unroll
            for (int j = 0; j < 8; ++j)
                pv[j] = *(const float4*)(sP + (qgB + 16 * j) * PB_STRIDE + k);
#pragma unroll
            for (int i = 0; i < 4; ++i)
                vv[i] = *(const float4*)(sVT + (dgB + 16 * i) * PB_STRIDE + k);
#pragma unroll
            for (int j = 0; j < 8; ++j) {
                const unsigned long long* pp = (const unsigned long long*)&pv[j];
#pragma unroll
                for (int i = 0; i < 4; ++i) {
                    const unsigned long long* vp = (const unsigned long long*)&vv[i];
                    acc2[j][i] = ffma2(pp[0], vp[0], acc2[j][i]);
                    acc2[j][i] = ffma2(pp[1], vp[1], acc2[j][i]);
                }
            }
        }
    }

    // write context
    {
#pragma unroll
        for (int j = 0; j < 8; ++j) {
            float* cdst = out_ctx + ((size_t)b * QQ + q0 + qgB + 16 * j) * DD + dgB;
#pragma unroll
            for (int i = 0; i < 4; ++i)
                __stcs(cdst + 16 * i, hsum2(acc2[j][i]));
        }
    }
}

extern "C" void kernel_launch(void* const* d_in, const int* in_sizes, int n_in,
                              void* d_out, int out_size)
{
    const float* q = (const float*)d_in[0];
    const float* k = (const float*)d_in[1];
    const float* v = (const float*)d_in[2];
    const unsigned char* mask = (const unsigned char*)d_in[3];

    float* ctx  = (float*)d_out;                 // [B,Q,D] first
    float* attn = ctx + (size_t)BB * QQ * DD;    // [B,Q,K] second

    detect_mask_dtype<<<1, 256>>>(mask);

    cudaFuncSetAttribute(sdpa_hyb_kernel,
                         cudaFuncAttributeMaxDynamicSharedMemorySize, SMEM_BYTES);
    dim3 grid(QQ / QT, BB);
    sdpa_hyb_kernel<<<grid, 256, SMEM_BYTES>>>(q, k, v, mask, ctx, attn);
}